// round 7
// baseline (speedup 1.0000x reference)
#include <cuda_runtime.h>

#define WPC   4            // warps per CTA (1 warp = 1 sample)
#define NTHR  (WPC * 32)
#define NSAMP 2048

struct FF {
    const float4* B; const float4* G; const float4* S; const int4* P;
};

// In-register 128-point Walsh-Hadamard, 4 elems/lane (e = lane*4 + r).
// Strides 1,2 intra-lane; strides 4..64 via shfl_xor on lane bits 0..4.
__device__ __forceinline__ void fwht4(float v[4], int lane) {
    float a0 = v[0] + v[1], a1 = v[0] - v[1];
    float a2 = v[2] + v[3], a3 = v[2] - v[3];
    v[0] = a0 + a2; v[2] = a0 - a2;
    v[1] = a1 + a3; v[3] = a1 - a3;
#pragma unroll
    for (int m = 1; m <= 16; m <<= 1) {
        float sgn = (lane & m) ? -1.0f : 1.0f;
#pragma unroll
        for (int r = 0; r < 4; r++) {
            float o = __shfl_xor_sync(0xffffffffu, v[r], m);
            v[r] = fmaf(sgn, v[r], o);   // lower: v+o ; upper: o-v
        }
    }
}

// v[e] = ffS[e] * FWHT( ffG[e] * u[ffP[e]] ) where u = FWHT(ffB * z/128).
// The 1/128 is pre-folded into zv (linear).
__device__ __forceinline__ void fastfood(
    int blk, const float zv[4], float* pbuf, float v[4], FF ff, int lane)
{
    int idx = blk * 32 + lane;
    float4 fb = ff.B[idx];
    v[0] = fb.x * zv[0]; v[1] = fb.y * zv[1];
    v[2] = fb.z * zv[2]; v[3] = fb.w * zv[3];
    fwht4(v, lane);
    reinterpret_cast<float4*>(pbuf)[lane] = make_float4(v[0], v[1], v[2], v[3]);
    __syncwarp();
    int4   p = ff.P[idx];
    float4 g = ff.G[idx];
    v[0] = g.x * pbuf[p.x];
    v[1] = g.y * pbuf[p.y];
    v[2] = g.z * pbuf[p.z];
    v[3] = g.w * pbuf[p.w];
    fwht4(v, lane);
    float4 s = ff.S[idx];
    v[0] *= s.x; v[1] *= s.y; v[2] *= s.z; v[3] *= s.w;
    __syncwarp();   // pbuf reusable by next call
}

__global__ void __launch_bounds__(NTHR)
mlp_fastfood_kernel(
    const float* __restrict__ x,  const float* __restrict__ z,
    const float* __restrict__ W0, const float* __restrict__ b0,
    const float* __restrict__ W1, const float* __restrict__ b1,
    const float* __restrict__ W2, const float* __restrict__ b2,
    const float* __restrict__ ffB, const float* __restrict__ ffG,
    const float* __restrict__ ffS, const int* __restrict__ ffP,
    float* __restrict__ out)
{
    __shared__ float sm[WPC * 256];          // per warp: 128 perm scratch + 128 acc
    const int lane   = threadIdx.x & 31;
    const int warp   = threadIdx.x >> 5;
    const int sample = blockIdx.x * WPC + warp;

    float* pbuf = sm + warp * 256;
    float* acc  = pbuf + 128;

    FF ff { reinterpret_cast<const float4*>(ffB),
            reinterpret_cast<const float4*>(ffG),
            reinterpret_cast<const float4*>(ffS),
            reinterpret_cast<const int4*>(ffP) };

    // z/128 held in registers for the whole kernel
    float4 zq = reinterpret_cast<const float4*>(z + (size_t)sample * 128)[lane];
    const float inv = 1.0f / 128.0f;
    float zv[4] = { zq.x * inv, zq.y * inv, zq.z * inv, zq.w * inv };

    // layer-0 input: col = (e & 31) = (lane&7)*4 + r
    float4 xq = reinterpret_cast<const float4*>(x + (size_t)sample * 32)[lane & 7];
    float hv[4] = { xq.x, xq.y, xq.z, xq.w };

    reinterpret_cast<float4*>(acc)[lane] = make_float4(0.f, 0.f, 0.f, 0.f);
    __syncwarp();

    float v[4];

    // ---------------- Layer 0: blocks 0..31 (weights) + 32 (bias) ----------------
    // block b covers rows 4b..4b+3 of W0[128x32]; e -> (row = b*4 + (lane>>3), col = e&31)
#pragma unroll 1
    for (int b = 0; b < 32; b++) {
        fastfood(b, zv, pbuf, v, ff, lane);
        float4 w = reinterpret_cast<const float4*>(W0)[b * 32 + lane];
        float t =      (v[0] + w.x) * hv[0];
        t = fmaf(v[1] + w.y, hv[1], t);
        t = fmaf(v[2] + w.z, hv[2], t);
        t = fmaf(v[3] + w.w, hv[3], t);
        t += __shfl_xor_sync(0xffffffffu, t, 1);
        t += __shfl_xor_sync(0xffffffffu, t, 2);
        t += __shfl_xor_sync(0xffffffffu, t, 4);
        if ((lane & 7) == 0) acc[b * 4 + (lane >> 3)] += t;
    }
    fastfood(32, zv, pbuf, v, ff, lane);      // bias delta
    {
        float4* a4 = reinterpret_cast<float4*>(acc);
        float4 a = a4[lane];
        a.x += v[0]; a.y += v[1]; a.z += v[2]; a.w += v[3];
        a4[lane] = a;
    }
    __syncwarp();
    {   // epilogue: h1 = relu(acc + b0) into registers; zero acc
        float4 a  = reinterpret_cast<float4*>(acc)[lane];
        float4 bb = reinterpret_cast<const float4*>(b0)[lane];
        hv[0] = fmaxf(a.x + bb.x, 0.f);
        hv[1] = fmaxf(a.y + bb.y, 0.f);
        hv[2] = fmaxf(a.z + bb.z, 0.f);
        hv[3] = fmaxf(a.w + bb.w, 0.f);
        reinterpret_cast<float4*>(acc)[lane] = make_float4(0.f, 0.f, 0.f, 0.f);
    }
    __syncwarp();

    // ---------------- Layer 1: blocks 33..160 (weights) + 161 (bias) --------------
    // block b == row b of W1[128x128]
#pragma unroll 1
    for (int b = 0; b < 128; b++) {
        fastfood(33 + b, zv, pbuf, v, ff, lane);
        float4 w = reinterpret_cast<const float4*>(W1)[b * 32 + lane];
        float t =      (v[0] + w.x) * hv[0];
        t = fmaf(v[1] + w.y, hv[1], t);
        t = fmaf(v[2] + w.z, hv[2], t);
        t = fmaf(v[3] + w.w, hv[3], t);
#pragma unroll
        for (int m = 1; m <= 16; m <<= 1)
            t += __shfl_xor_sync(0xffffffffu, t, m);
        if (lane == 0) acc[b] += t;
    }
    fastfood(161, zv, pbuf, v, ff, lane);
    {
        float4* a4 = reinterpret_cast<float4*>(acc);
        float4 a = a4[lane];
        a.x += v[0]; a.y += v[1]; a.z += v[2]; a.w += v[3];
        a4[lane] = a;
    }
    __syncwarp();
    {
        float4 a  = reinterpret_cast<float4*>(acc)[lane];
        float4 bb = reinterpret_cast<const float4*>(b1)[lane];
        hv[0] = fmaxf(a.x + bb.x, 0.f);
        hv[1] = fmaxf(a.y + bb.y, 0.f);
        hv[2] = fmaxf(a.z + bb.z, 0.f);
        hv[3] = fmaxf(a.w + bb.w, 0.f);
        reinterpret_cast<float4*>(acc)[lane] = make_float4(0.f, 0.f, 0.f, 0.f);
    }
    __syncwarp();

    // ---------------- Layer 2: blocks 162..177 (weights) + 178 (bias) -------------
    // block b == row b of W2[16x128]; no relu; only first 16 of bias block used
#pragma unroll 1
    for (int b = 0; b < 16; b++) {
        fastfood(162 + b, zv, pbuf, v, ff, lane);
        float4 w = reinterpret_cast<const float4*>(W2)[b * 32 + lane];
        float t =      (v[0] + w.x) * hv[0];
        t = fmaf(v[1] + w.y, hv[1], t);
        t = fmaf(v[2] + w.z, hv[2], t);
        t = fmaf(v[3] + w.w, hv[3], t);
#pragma unroll
        for (int m = 1; m <= 16; m <<= 1)
            t += __shfl_xor_sync(0xffffffffu, t, m);
        if (lane == 0) acc[b] += t;
    }
    fastfood(178, zv, pbuf, v, ff, lane);
    if (lane < 4) {                           // e = lane*4+r < 16
        float4* a4 = reinterpret_cast<float4*>(acc);
        float4 a = a4[lane];
        a.x += v[0]; a.y += v[1]; a.z += v[2]; a.w += v[3];
        a4[lane] = a;
    }
    __syncwarp();
    if (lane < 4) {
        float4 a  = reinterpret_cast<float4*>(acc)[lane];
        float4 bb = reinterpret_cast<const float4*>(b2)[lane];
        float4 o  = make_float4(a.x + bb.x, a.y + bb.y, a.z + bb.z, a.w + bb.w);
        reinterpret_cast<float4*>(out + (size_t)sample * 16)[lane] = o;
    }
}

extern "C" void kernel_launch(void* const* d_in, const int* in_sizes, int n_in,
                              void* d_out, int out_size)
{
    const float* x   = (const float*)d_in[0];
    const float* z   = (const float*)d_in[1];
    const float* W0  = (const float*)d_in[2];
    const float* b0  = (const float*)d_in[3];
    const float* W1  = (const float*)d_in[4];
    const float* b1  = (const float*)d_in[5];
    const float* W2  = (const float*)d_in[6];
    const float* b2  = (const float*)d_in[7];
    const float* ffB = (const float*)d_in[8];
    const float* ffG = (const float*)d_in[9];
    const float* ffS = (const float*)d_in[10];
    const int*   ffP = (const int*)d_in[11];

    mlp_fastfood_kernel<<<NSAMP / WPC, NTHR>>>(
        x, z, W0, b0, W1, b1, W2, b2, ffB, ffG, ffS, ffP, (float*)d_out);
}

// round 9
// speedup vs baseline: 1.3557x; 1.3557x over previous
#include <cuda_runtime.h>

#define NWARP 8            // warps per CTA; 1 CTA = 1 sample
#define NTHR  (NWARP * 32)
#define NSAMP 2048

struct FF {
    const float4* B; const float4* G; const float4* S; const int4* P;
};

// In-register 128-point Walsh-Hadamard, 4 elems/lane (e = lane*4 + r).
// Strides 1,2 intra-lane; strides 4..64 via shfl_xor on lane bits 0..4.
__device__ __forceinline__ void fwht4(float v[4], int lane) {
    float a0 = v[0] + v[1], a1 = v[0] - v[1];
    float a2 = v[2] + v[3], a3 = v[2] - v[3];
    v[0] = a0 + a2; v[2] = a0 - a2;
    v[1] = a1 + a3; v[3] = a1 - a3;
#pragma unroll
    for (int m = 1; m <= 16; m <<= 1) {
        float sgn = (lane & m) ? -1.0f : 1.0f;
#pragma unroll
        for (int r = 0; r < 4; r++) {
            float o = __shfl_xor_sync(0xffffffffu, v[r], m);
            v[r] = fmaf(sgn, v[r], o);   // lower: v+o ; upper: o-v
        }
    }
}

// v[e] = ffS[e] * FWHT( ffG[e] * u[ffP[e]] ) where u = FWHT(ffB * z/128).
// The 1/128 is pre-folded into zv (linear).
__device__ __forceinline__ void fastfood(
    int blk, const float zv[4], float* pbuf, float v[4], FF ff, int lane)
{
    int idx = blk * 32 + lane;
    float4 fb = ff.B[idx];
    v[0] = fb.x * zv[0]; v[1] = fb.y * zv[1];
    v[2] = fb.z * zv[2]; v[3] = fb.w * zv[3];
    fwht4(v, lane);
    reinterpret_cast<float4*>(pbuf)[lane] = make_float4(v[0], v[1], v[2], v[3]);
    __syncwarp();
    int4   p = ff.P[idx];
    float4 g = ff.G[idx];
    v[0] = g.x * pbuf[p.x];
    v[1] = g.y * pbuf[p.y];
    v[2] = g.z * pbuf[p.z];
    v[3] = g.w * pbuf[p.w];
    fwht4(v, lane);
    float4 s = ff.S[idx];
    v[0] *= s.x; v[1] *= s.y; v[2] *= s.z; v[3] *= s.w;
    __syncwarp();   // pbuf reusable by next call
}

__global__ void __launch_bounds__(NTHR)
mlp_fastfood_kernel(
    const float* __restrict__ x,  const float* __restrict__ z,
    const float* __restrict__ W0, const float* __restrict__ b0,
    const float* __restrict__ W1, const float* __restrict__ b1,
    const float* __restrict__ W2, const float* __restrict__ b2,
    const float* __restrict__ ffB, const float* __restrict__ ffG,
    const float* __restrict__ ffS, const int* __restrict__ ffP,
    float* __restrict__ out)
{
    __shared__ float pbuf_s[NWARP * 128];   // per-warp permutation scratch
    __shared__ float accW[128];             // weight-block results (disjoint writers)
    __shared__ float accB[128];             // bias-block result (single writer warp)

    const int lane   = threadIdx.x & 31;
    const int warp   = threadIdx.x >> 5;
    const int sample = blockIdx.x;

    float* pbuf = pbuf_s + warp * 128;

    FF ff { reinterpret_cast<const float4*>(ffB),
            reinterpret_cast<const float4*>(ffG),
            reinterpret_cast<const float4*>(ffS),
            reinterpret_cast<const int4*>(ffP) };

    // z/128 held in registers for the whole kernel (redundant per warp; L1 hit)
    float4 zq = reinterpret_cast<const float4*>(z + (size_t)sample * 128)[lane];
    const float inv = 1.0f / 128.0f;
    float zv[4] = { zq.x * inv, zq.y * inv, zq.z * inv, zq.w * inv };

    // layer-0 input: col = (e & 31) = (lane&7)*4 + r
    float4 xq = reinterpret_cast<const float4*>(x + (size_t)sample * 32)[lane & 7];
    float hv[4] = { xq.x, xq.y, xq.z, xq.w };

    float v[4];

    // ---------------- Layer 0: weight blocks 0..31, bias block 32 ----------------
    // weight block b covers rows 4b..4b+3 of W0[128x32]; warp owns b in [4w, 4w+4)
#pragma unroll 1
    for (int i = 0; i < 4; i++) {
        int b = warp * 4 + i;
        fastfood(b, zv, pbuf, v, ff, lane);
        float4 w = reinterpret_cast<const float4*>(W0)[b * 32 + lane];
        float t =      (v[0] + w.x) * hv[0];
        t = fmaf(v[1] + w.y, hv[1], t);
        t = fmaf(v[2] + w.z, hv[2], t);
        t = fmaf(v[3] + w.w, hv[3], t);
        t += __shfl_xor_sync(0xffffffffu, t, 1);
        t += __shfl_xor_sync(0xffffffffu, t, 2);
        t += __shfl_xor_sync(0xffffffffu, t, 4);
        if ((lane & 7) == 0) accW[b * 4 + (lane >> 3)] = t;
    }
    if (warp == 0) {                          // bias delta block
        fastfood(32, zv, pbuf, v, ff, lane);
        reinterpret_cast<float4*>(accB)[lane] = make_float4(v[0], v[1], v[2], v[3]);
    }
    __syncthreads();
    {   // epilogue (every warp builds its own copy of h1)
        float4 aw = reinterpret_cast<float4*>(accW)[lane];
        float4 ab = reinterpret_cast<float4*>(accB)[lane];
        float4 bb = reinterpret_cast<const float4*>(b0)[lane];
        hv[0] = fmaxf(aw.x + ab.x + bb.x, 0.f);
        hv[1] = fmaxf(aw.y + ab.y + bb.y, 0.f);
        hv[2] = fmaxf(aw.z + ab.z + bb.z, 0.f);
        hv[3] = fmaxf(aw.w + ab.w + bb.w, 0.f);
    }
    __syncthreads();   // all reads done before L1 overwrites acc

    // ---------------- Layer 1: weight blocks 33..160, bias block 161 -------------
    // weight block j (0..127) == row j of W1[128x128]; warp owns j in [16w, 16w+16)
#pragma unroll 1
    for (int i = 0; i < 16; i++) {
        int j = warp * 16 + i;
        fastfood(33 + j, zv, pbuf, v, ff, lane);
        float4 w = reinterpret_cast<const float4*>(W1)[j * 32 + lane];
        float t =      (v[0] + w.x) * hv[0];
        t = fmaf(v[1] + w.y, hv[1], t);
        t = fmaf(v[2] + w.z, hv[2], t);
        t = fmaf(v[3] + w.w, hv[3], t);
#pragma unroll
        for (int m = 1; m <= 16; m <<= 1)
            t += __shfl_xor_sync(0xffffffffu, t, m);
        if (lane == 0) accW[j] = t;
    }
    if (warp == 1) {
        fastfood(161, zv, pbuf, v, ff, lane);
        reinterpret_cast<float4*>(accB)[lane] = make_float4(v[0], v[1], v[2], v[3]);
    }
    __syncthreads();
    {
        float4 aw = reinterpret_cast<float4*>(accW)[lane];
        float4 ab = reinterpret_cast<float4*>(accB)[lane];
        float4 bb = reinterpret_cast<const float4*>(b1)[lane];
        hv[0] = fmaxf(aw.x + ab.x + bb.x, 0.f);
        hv[1] = fmaxf(aw.y + ab.y + bb.y, 0.f);
        hv[2] = fmaxf(aw.z + ab.z + bb.z, 0.f);
        hv[3] = fmaxf(aw.w + ab.w + bb.w, 0.f);
    }
    __syncthreads();

    // ---------------- Layer 2: weight blocks 162..177, bias block 178 ------------
    // weight block j (0..15) == row j of W2[16x128]; warp owns j in {2w, 2w+1}
#pragma unroll 1
    for (int i = 0; i < 2; i++) {
        int j = warp * 2 + i;
        fastfood(162 + j, zv, pbuf, v, ff, lane);
        float4 w = reinterpret_cast<const float4*>(W2)[j * 32 + lane];
        float t =      (v[0] + w.x) * hv[0];
        t = fmaf(v[1] + w.y, hv[1], t);
        t = fmaf(v[2] + w.z, hv[2], t);
        t = fmaf(v[3] + w.w, hv[3], t);
#pragma unroll
        for (int m = 1; m <= 16; m <<= 1)
            t += __shfl_xor_sync(0xffffffffu, t, m);
        if (lane == 0) accW[j] = t;
    }
    if (warp == 2) {
        fastfood(178, zv, pbuf, v, ff, lane);
        reinterpret_cast<float4*>(accB)[lane] = make_float4(v[0], v[1], v[2], v[3]);
    }
    __syncthreads();
    if (warp == 0 && lane < 4) {              // e = lane*4+r < 16
        float4 aw = reinterpret_cast<float4*>(accW)[lane];
        float4 ab = reinterpret_cast<float4*>(accB)[lane];
        float4 bb = reinterpret_cast<const float4*>(b2)[lane];
        float4 o  = make_float4(aw.x + ab.x + bb.x, aw.y + ab.y + bb.y,
                                aw.z + ab.z + bb.z, aw.w + ab.w + bb.w);
        reinterpret_cast<float4*>(out + (size_t)sample * 16)[lane] = o;
    }
}

extern "C" void kernel_launch(void* const* d_in, const int* in_sizes, int n_in,
                              void* d_out, int out_size)
{
    const float* x   = (const float*)d_in[0];
    const float* z   = (const float*)d_in[1];
    const float* W0  = (const float*)d_in[2];
    const float* b0  = (const float*)d_in[3];
    const float* W1  = (const float*)d_in[4];
    const float* b1  = (const float*)d_in[5];
    const float* W2  = (const float*)d_in[6];
    const float* b2  = (const float*)d_in[7];
    const float* ffB = (const float*)d_in[8];
    const float* ffG = (const float*)d_in[9];
    const float* ffS = (const float*)d_in[10];
    const int*   ffP = (const int*)d_in[11];

    mlp_fastfood_kernel<<<NSAMP, NTHR>>>(
        x, z, W0, b0, W1, b1, W2, b2, ffB, ffG, ffS, ffP, (float*)d_out);
}